// round 16
// baseline (speedup 1.0000x reference)
#include <cuda_runtime.h>
#include <cuda_bf16.h>
#include <cstdint>

#define NB   2
#define NS   1024
#define ND   1024
#define NH   16
#define NHD  64
#define NNC  64
#define NCB  16
#define NSB  8
#define NJ   2
#define NWIN 256

#define INVS 0.125f
#define NEG  (-1e30f)

#define KA   1024
#define BM   128
#define BN   128
#define BK   32
#define AST  40
#define NIT3 96
#define NSTG 6
#define STAGE_BYTES ((BM + BN) * AST * 2)       // 20480
#define SMEM_GEMM   (NSTG * STAGE_BYTES)        // 122880

#define TS   68
#define PS   65
#define SMEM_ATT ((3 * 64 * TS + 64 * PS) * 4)

// ---------------- scratch ----------------
__device__ __align__(16) float g_q [NB*NS*ND];
__device__ __align__(16) float g_k [NB*NS*ND];
__device__ __align__(16) float g_v [NB*NS*ND];
__device__ __align__(16) float g_ck[NB*NNC*ND];
__device__ __align__(16) float g_cv[NB*NNC*ND];
__device__ __align__(16) float g_oc[NB*NS*ND];
__device__ __align__(16) float g_os[NB*NS*ND];
__device__ __align__(16) float g_ow[NB*NS*ND];
__device__ int   g_top[NB*NS*NJ];
__device__ __align__(16) float g_gates[NB*NS*3];
__device__ __align__(16) __nv_bfloat16 g_ah[(size_t)NB*NS*ND];
__device__ __align__(16) __nv_bfloat16 g_al[(size_t)NB*NS*ND];
__device__ __align__(16) __nv_bfloat16 g_wh[(size_t)3*ND*ND];
__device__ __align__(16) __nv_bfloat16 g_wl[(size_t)3*ND*ND];
__device__ __align__(16) __nv_bfloat16 g_woh[(size_t)ND*ND];
__device__ __align__(16) __nv_bfloat16 g_wol[(size_t)ND*ND];
__device__ __align__(16) float g_xkc[NB*NNC*ND];
__device__ __align__(16) float g_xvc[NB*NNC*ND];
__device__ __align__(16) float g_pec[ND];
__device__ __align__(16) float g_pvc[ND];
__device__ __align__(16) float g_tt [NB*NNC*ND];
__device__ __align__(16) float g_imp[NB*NS*NNC];
__device__ __align__(16) float g_cp  [2*4*128*1024];
__device__ __align__(16) float g_ttp [2*4*64*1024];
__device__ __align__(16) float g_impp[2*4*1024*64];

// ======================= PTX helpers ================================================
__device__ __forceinline__ void cp16(uint32_t d, const void* s) {
    asm volatile("cp.async.cg.shared.global [%0], [%1], 16;" :: "r"(d), "l"(s));
}
__device__ __forceinline__ void cp_commit() {
    asm volatile("cp.async.commit_group;");
}
__device__ __forceinline__ void cp_wait1() {
    asm volatile("cp.async.wait_group 1;");
}
__device__ __forceinline__ void cp_wait3() {
    asm volatile("cp.async.wait_group 3;");
}
__device__ __forceinline__ void ldsm_x4(uint32_t& r0, uint32_t& r1, uint32_t& r2, uint32_t& r3,
                                        uint32_t addr) {
    asm volatile("ldmatrix.sync.aligned.m8n8.x4.shared.b16 {%0,%1,%2,%3}, [%4];"
        : "=r"(r0), "=r"(r1), "=r"(r2), "=r"(r3) : "r"(addr));
}
__device__ __forceinline__ void mma16816(float* c, const uint32_t* a, const uint32_t* b) {
    asm volatile("mma.sync.aligned.m16n8k16.row.col.f32.bf16.bf16.f32 "
        "{%0,%1,%2,%3}, {%4,%5,%6,%7}, {%8,%9}, {%0,%1,%2,%3};"
        : "+f"(c[0]), "+f"(c[1]), "+f"(c[2]), "+f"(c[3])
        : "r"(a[0]), "r"(a[1]), "r"(a[2]), "r"(a[3]), "r"(b[0]), "r"(b[1]));
}

// ======================= split conversions =========================================
__global__ __launch_bounds__(256) void split_kernel(
    const float* __restrict__ src, __nv_bfloat16* __restrict__ hi,
    __nv_bfloat16* __restrict__ lo)
{
    int idx = (blockIdx.x * 256 + threadIdx.x) * 4;
    float4 v = *(const float4*)(src + idx);
    __nv_bfloat16 h0 = __float2bfloat16(v.x), h1 = __float2bfloat16(v.y);
    __nv_bfloat16 h2 = __float2bfloat16(v.z), h3 = __float2bfloat16(v.w);
    *(__nv_bfloat162*)(hi + idx)     = __halves2bfloat162(h0, h1);
    *(__nv_bfloat162*)(hi + idx + 2) = __halves2bfloat162(h2, h3);
    *(__nv_bfloat162*)(lo + idx) = __halves2bfloat162(
        __float2bfloat16(v.x - __bfloat162float(h0)),
        __float2bfloat16(v.y - __bfloat162float(h1)));
    *(__nv_bfloat162*)(lo + idx + 2) = __halves2bfloat162(
        __float2bfloat16(v.z - __bfloat162float(h2)),
        __float2bfloat16(v.w - __bfloat162float(h3)));
}

__global__ __launch_bounds__(256) void convert_w3_kernel(
    const float* __restrict__ W0, const float* __restrict__ W1,
    const float* __restrict__ W2,
    __nv_bfloat16* __restrict__ Wh, __nv_bfloat16* __restrict__ Wl)
{
    const int z = blockIdx.z;
    const float* W = (z == 0) ? W0 : (z == 1) ? W1 : W2;
    const int row_off = z * 1024;

    __shared__ float t[32][33];
    int n0 = blockIdx.x * 32, k0 = blockIdx.y * 32;
    int tx = threadIdx.x & 31, ty = threadIdx.x >> 5;
#pragma unroll
    for (int i = 0; i < 32; i += 8)
        t[ty + i][tx] = W[(k0 + ty + i) * 1024 + n0 + tx];
    __syncthreads();
#pragma unroll
    for (int i = 0; i < 32; i += 8) {
        int n = row_off + n0 + ty + i, k = k0 + tx;
        float v = t[tx][ty + i];
        __nv_bfloat16 h = __float2bfloat16(v);
        Wh[(size_t)n * 1024 + k] = h;
        Wl[(size_t)n * 1024 + k] = __float2bfloat16(v - __bfloat162float(h));
    }
}

__global__ __launch_bounds__(256) void convert_w1_kernel(
    const float* __restrict__ W,
    __nv_bfloat16* __restrict__ Wh, __nv_bfloat16* __restrict__ Wl)
{
    __shared__ float t[32][33];
    int n0 = blockIdx.x * 32, k0 = blockIdx.y * 32;
    int tx = threadIdx.x & 31, ty = threadIdx.x >> 5;
#pragma unroll
    for (int i = 0; i < 32; i += 8)
        t[ty + i][tx] = W[(k0 + ty + i) * 1024 + n0 + tx];
    __syncthreads();
#pragma unroll
    for (int i = 0; i < 32; i += 8) {
        int n = n0 + ty + i, k = k0 + tx;
        float v = t[tx][ty + i];
        __nv_bfloat16 h = __float2bfloat16(v);
        Wh[(size_t)n * 1024 + k] = h;
        Wl[(size_t)n * 1024 + k] = __float2bfloat16(v - __bfloat162float(h));
    }
}

// ============ fused 3-term HMMA GEMM (6-stage, reg double-buffered, unroll x2) ======
__global__ void __launch_bounds__(256) mma_gemm3_kernel(
    const __nv_bfloat16* __restrict__ Ah, const __nv_bfloat16* __restrict__ Al,
    const __nv_bfloat16* __restrict__ Wh, const __nv_bfloat16* __restrict__ Wl,
    float* __restrict__ Cq, float* __restrict__ Ck, float* __restrict__ Cv,
    const float* __restrict__ extra, int qkv_mode)
{
    extern __shared__ __nv_bfloat16 smem[];

    const int tid = threadIdx.x;
    const int wid = tid >> 5, lane = tid & 31;
    const int wm = wid >> 2, wn = wid & 3;
    const int mt = blockIdx.y * BM, nt = blockIdx.x * BN;

    const uint32_t sb = (uint32_t)__cvta_generic_to_shared(smem);
    const uint32_t B_OFF = BM * AST * 2;

    const int lrow = tid >> 1;
    const int lc   = (tid & 1) * 2;
    const size_t aoff = (size_t)(mt + lrow) * KA + lc * 8;
    const size_t boff = (size_t)(nt + lrow) * KA + lc * 8;
    const __nv_bfloat16* aSrc[2] = {Ah + aoff, Al + aoff};
    const __nv_bfloat16* bSrc[2] = {Wh + boff, Wl + boff};
    const uint32_t dA = sb + (lrow * AST + lc * 8) * 2;
    const uint32_t dB = sb + B_OFF + (lrow * AST + lc * 8) * 2;

    float c[4][4][4];
#pragma unroll
    for (int i = 0; i < 4; i++)
#pragma unroll
        for (int j = 0; j < 4; j++)
#pragma unroll
            for (int r = 0; r < 4; r++) c[i][j][r] = 0.f;

    const int al  = lane & 15;
    const int ahi = lane >> 4;

    uint32_t a0[4][4], b0[4][2], a1[4][4], b1[4][2];

#define ISSUE(j) do {                                                       \
        const int t_  = (j) >> 5;                                           \
        const int k0_ = ((j) & 31) * BK;                                    \
        const __nv_bfloat16* ga_ = aSrc[t_ == 2 ? 1 : 0] + k0_;             \
        const __nv_bfloat16* gb_ = bSrc[t_ == 1 ? 1 : 0] + k0_;             \
        const uint32_t so_ = ((j) % NSTG) * STAGE_BYTES;                    \
        cp16(dA + so_, ga_);       cp16(dA + so_ + 16, ga_ + 8);            \
        cp16(dB + so_, gb_);       cp16(dB + so_ + 16, gb_ + 8);            \
    } while (0)

#define LOADF(A_, B_, sA_, sB_, kg_) do {                                   \
        _Pragma("unroll")                                                   \
        for (int i_ = 0; i_ < 4; i_++) {                                    \
            uint32_t ad_ = (sA_) + ((wm * 64 + i_ * 16 + al) * AST + (kg_) * 8) * 2; \
            ldsm_x4(A_[i_][0], A_[i_][1], A_[i_][2], A_[i_][3], ad_);       \
        }                                                                   \
        _Pragma("unroll")                                                   \
        for (int jj_ = 0; jj_ < 2; jj_++) {                                 \
            uint32_t bd_ = (sB_) + ((wn * 32 + jj_ * 16 + al) * AST + (kg_) * 8) * 2; \
            uint32_t r0_, r1_, r2_, r3_;                                    \
            ldsm_x4(r0_, r1_, r2_, r3_, bd_);                               \
            B_[jj_ * 2 + 0][0] = r0_; B_[jj_ * 2 + 1][0] = r1_;             \
            B_[jj_ * 2 + 0][1] = r2_; B_[jj_ * 2 + 1][1] = r3_;             \
        }                                                                   \
    } while (0)

#define MMAF(A_, B_) do {                                                   \
        _Pragma("unroll")                                                   \
        for (int i_ = 0; i_ < 4; i_++)                                      \
            _Pragma("unroll")                                               \
            for (int j_ = 0; j_ < 4; j_++) mma16816(c[i_][j_], A_[i_], B_[j_]); \
    } while (0)

    // prologue: issue 4 groups, preload (it=0, ks=0) fragments
    ISSUE(0); cp_commit();
    ISSUE(1); cp_commit();
    ISSUE(2); cp_commit();
    ISSUE(3); cp_commit();
    cp_wait3();
    __syncthreads();
    LOADF(a0, b0, sb, sb + B_OFF, ahi);

    for (int it = 0; it < NIT3; it += 2) {
        cp_wait1();                        // slots it..it+2 resident
        __syncthreads();
        if (it + 4 < NIT3) { ISSUE(it + 4); }
        cp_commit();
        if (it + 5 < NIT3) { ISSUE(it + 5); }
        cp_commit();

        const uint32_t sA0 = sb + ((it)     % NSTG) * STAGE_BYTES;
        const uint32_t sB0 = sA0 + B_OFF;
        const uint32_t sA1 = sb + ((it + 1) % NSTG) * STAGE_BYTES;
        const uint32_t sB1 = sA1 + B_OFF;
        const uint32_t sA2 = sb + ((it + 2) % NSTG) * STAGE_BYTES;
        const uint32_t sB2 = sA2 + B_OFF;

        LOADF(a1, b1, sA0, sB0, 2 + ahi);  // (it,   ks1)
        MMAF(a0, b0);                      // (it,   ks0)
        LOADF(a0, b0, sA1, sB1, ahi);      // (it+1, ks0)
        MMAF(a1, b1);                      // (it,   ks1)
        LOADF(a1, b1, sA1, sB1, 2 + ahi);  // (it+1, ks1)
        MMAF(a0, b0);                      // (it+1, ks0)
        if (it + 2 < NIT3)
            LOADF(a0, b0, sA2, sB2, ahi);  // (it+2, ks0) — cross-iter prefetch
        MMAF(a1, b1);                      // (it+1, ks1)
    }
#undef ISSUE
#undef LOADF
#undef MMAF

    float* dst;
    bool add_pe = false;
    int ncol0;
    if (qkv_mode) {
        const int seg = nt >> 10;
        dst = (seg == 0) ? Cq : (seg == 1 ? Ck : Cv);
        add_pe = (seg != 0);
        ncol0 = nt & 1023;
    } else {
        dst = Cq;
        ncol0 = nt;
    }

    const int mbase = mt + wm * 64;
    const int nbase = ncol0 + wn * 32;
    const int rr = lane >> 2, cc = (lane & 3) * 2;
#pragma unroll
    for (int i = 0; i < 4; i++) {
#pragma unroll
        for (int j = 0; j < 4; j++) {
            int row = mbase + i * 16 + rr;
            int col = nbase + j * 8 + cc;
            float2 v0 = make_float2(c[i][j][0], c[i][j][1]);
            float2 v1 = make_float2(c[i][j][2], c[i][j][3]);
            if (qkv_mode) {
                if (add_pe) {
                    const float* p0 = extra + (row & 15) * 1024 + col;
                    const float* p1 = extra + ((row + 8) & 15) * 1024 + col;
                    v0.x += p0[0]; v0.y += p0[1];
                    v1.x += p1[0]; v1.y += p1[1];
                }
            } else {
                v0.x += extra[col]; v0.y += extra[col + 1];
                v1.x += extra[col]; v1.y += extra[col + 1];
            }
            *(float2*)(dst + (size_t)row * 1024 + col)       = v0;
            *(float2*)(dst + (size_t)(row + 8) * 1024 + col) = v1;
        }
    }
}

// ======================= fp32 SGEMM, K-split x4 (ck/cv partials) ====================
__global__ __launch_bounds__(256) void csgemm_kernel(
    const float* __restrict__ Ak, const float* __restrict__ Av,
    const float* __restrict__ Wk, const float* __restrict__ Wv)
{
    const int path = blockIdx.z >> 2, kc = blockIdx.z & 3;
    const float* A  = path ? Av : Ak;
    const float* Bm = path ? Wv : Wk;
    float* C = g_cp + (size_t)blockIdx.z * (128 * 1024);

    __shared__ float As[16][132];
    __shared__ float Bs[16][64];

    const int tid = threadIdx.x;
    const int bn  = blockIdx.x * 64;
    const int tx  = tid & 15;
    const int ty  = tid >> 4;

    const int arow = tid >> 1;
    const int acol = (tid & 1) * 8;
    const int brow = tid >> 4;
    const int bcol = (tid & 15) * 4;

    float acc[8][4];
#pragma unroll
    for (int i = 0; i < 8; i++)
#pragma unroll
        for (int j = 0; j < 4; j++) acc[i][j] = 0.f;

    const int kbeg = kc * 256, kend = kbeg + 256;
    for (int k0 = kbeg; k0 < kend; k0 += 16) {
        float4 a0 = *(const float4*)(A + arow * 1024 + k0 + acol);
        float4 a1 = *(const float4*)(A + arow * 1024 + k0 + acol + 4);
        As[acol+0][arow] = a0.x; As[acol+1][arow] = a0.y;
        As[acol+2][arow] = a0.z; As[acol+3][arow] = a0.w;
        As[acol+4][arow] = a1.x; As[acol+5][arow] = a1.y;
        As[acol+6][arow] = a1.z; As[acol+7][arow] = a1.w;
        float4 b4 = *(const float4*)(Bm + (k0 + brow) * 1024 + bn + bcol);
        *(float4*)&Bs[brow][bcol] = b4;
        __syncthreads();

#pragma unroll
        for (int kk = 0; kk < 16; kk++) {
            float4 t0 = *(const float4*)&As[kk][ty * 8];
            float4 t1 = *(const float4*)&As[kk][ty * 8 + 4];
            float4 bb = *(const float4*)&Bs[kk][tx * 4];
            float ar[8] = {t0.x, t0.y, t0.z, t0.w, t1.x, t1.y, t1.z, t1.w};
            float br[4] = {bb.x, bb.y, bb.z, bb.w};
#pragma unroll
            for (int i = 0; i < 8; i++)
#pragma unroll
                for (int j = 0; j < 4; j++) acc[i][j] += ar[i] * br[j];
        }
        __syncthreads();
    }

#pragma unroll
    for (int i = 0; i < 8; i++) {
        int m = ty * 8 + i;
#pragma unroll
        for (int j = 0; j < 4; j++)
            C[m * 1024 + bn + tx * 4 + j] = acc[i][j];
    }
}

__global__ __launch_bounds__(256) void reduce_ckcv_kernel(
    const float* __restrict__ bk, const float* __restrict__ bv)
{
    int idx = blockIdx.x * 256 + threadIdx.x;
    int path = idx >> 17, off = idx & 131071;
    const float* P = g_cp + (size_t)path * 4 * 131072;
    float s = P[off] + P[131072 + off] + P[2 * 131072 + off] + P[3 * 131072 + off];
    s += (path ? bv : bk)[off & 1023];
    (path ? g_cv : g_ck)[off] = s;
}

// ======================= fp32 NT GEMM, K-split x4 ===================================
__global__ __launch_bounds__(256) void nt_gemm_kernel(
    const float* __restrict__ A, const float* __restrict__ B, float* __restrict__ C,
    int N, long aB, long bB, long cB)
{
    const int b = blockIdx.z >> 2, kc = blockIdx.z & 3;
    const float* Ab = A + (size_t)b * aB;
    const float* Bb = B + (size_t)b * bB;
    float* Cb = C + (size_t)blockIdx.z * cB;

    __shared__ float As[64][33];
    __shared__ float Bs[64][33];

    const int tid = threadIdx.x;
    const int row = tid >> 2;
    const int c4  = (tid & 3) * 8;
    const int ty = tid >> 4, tx = tid & 15;
    const int i0 = blockIdx.y * 64, j0 = blockIdx.x * 64;

    float acc[4][4];
#pragma unroll
    for (int i = 0; i < 4; i++)
#pragma unroll
        for (int j = 0; j < 4; j++) acc[i][j] = 0.f;

    const int kbeg = kc * 256, kend = kbeg + 256;
    for (int k0 = kbeg; k0 < kend; k0 += 32) {
        float4 a0 = *(const float4*)(Ab + (size_t)(i0 + row) * 1024 + k0 + c4);
        float4 a1 = *(const float4*)(Ab + (size_t)(i0 + row) * 1024 + k0 + c4 + 4);
        As[row][c4+0] = a0.x; As[row][c4+1] = a0.y;
        As[row][c4+2] = a0.z; As[row][c4+3] = a0.w;
        As[row][c4+4] = a1.x; As[row][c4+5] = a1.y;
        As[row][c4+6] = a1.z; As[row][c4+7] = a1.w;
        float4 b0 = *(const float4*)(Bb + (size_t)(j0 + row) * 1024 + k0 + c4);
        float4 b1 = *(const float4*)(Bb + (size_t)(j0 + row) * 1024 + k0 + c4 + 4);
        Bs[row][c4+0] = b0.x; Bs[row][c4+1] = b0.y;
        Bs[row][c4+2] = b0.z; Bs[row][c4+3] = b0.w;
        Bs[row][c4+4] = b1.x; Bs[row][c4+5] = b1.y;
        Bs[row][c4+6] = b1.z; Bs[row][c4+7] = b1.w;
        __syncthreads();

#pragma unroll 8
        for (int k = 0; k < 32; k++) {
            float ar[4], br[4];
#pragma unroll
            for (int i = 0; i < 4; i++) ar[i] = As[ty * 4 + i][k];
#pragma unroll
            for (int j = 0; j < 4; j++) br[j] = Bs[tx * 4 + j][k];
#pragma unroll
            for (int i = 0; i < 4; i++)
#pragma unroll
                for (int j = 0; j < 4; j++) acc[i][j] += ar[i] * br[j];
        }
        __syncthreads();
    }

#pragma unroll
    for (int i = 0; i < 4; i++)
#pragma unroll
        for (int j = 0; j < 4; j++)
            Cb[(size_t)(i0 + ty * 4 + i) * N + j0 + tx * 4 + j] = acc[i][j];
}

__global__ __launch_bounds__(256) void reduce4_kernel(
    const float* __restrict__ P, float* __restrict__ out, int n)
{
    int idx = blockIdx.x * 256 + threadIdx.x;
    int b = idx / n, off = idx - b * n;
    const float* Pb = P + (size_t)b * 4 * n;
    out[idx] = Pb[off] + Pb[n + off] + Pb[2 * n + off] + Pb[3 * n + off];
}

// ---------------- exact compressed-row inputs ---------------------------------------
__global__ __launch_bounds__(256) void xc_kernel(
    const float* __restrict__ x, const float* __restrict__ wkc,
    const float* __restrict__ wvc)
{
    int idx = blockIdx.x * 256 + threadIdx.x;
    int d = idx & 1023;
    int n = (idx >> 10) & 63;
    int b = idx >> 16;
    const float* xb = x + ((size_t)(b * NS + n * NCB)) * ND + d;
    float sk = 0.f, sv = 0.f;
#pragma unroll
    for (int t = 0; t < NCB; t++) {
        float xv = xb[t * ND];
        sk += wkc[t] * xv;
        sv += wvc[t] * xv;
    }
    g_xkc[idx] = sk;
    g_xvc[idx] = sv;
}

__global__ __launch_bounds__(256) void pe_comb_kernel(
    const float* __restrict__ wpe, const float* __restrict__ wkc,
    const float* __restrict__ wvc)
{
    int d = blockIdx.x * 256 + threadIdx.x;
    float sk = 0.f, sv = 0.f;
#pragma unroll
    for (int t = 0; t < NCB; t++) {
        float p = wpe[t * ND + d];
        sk += wkc[t] * p;
        sv += wvc[t] * p;
    }
    g_pec[d] = sk;
    g_pvc[d] = sv;
}

// ---------------- top-2 ---------------------------------------------------------------
__global__ __launch_bounds__(256) void top2_kernel()
{
    const int bs = blockIdx.x * 8 + (threadIdx.x >> 5);
    const int lane = threadIdx.x & 31;
    const float* row = g_imp + (size_t)bs * 64;
    float v0 = row[lane], v1 = row[lane + 32];

    float bv; int bi;
    if (v0 >= v1) { bv = v0; bi = lane; } else { bv = v1; bi = lane + 32; }
#pragma unroll
    for (int off = 16; off > 0; off >>= 1) {
        float ov = __shfl_xor_sync(0xffffffffu, bv, off);
        int   oi = __shfl_xor_sync(0xffffffffu, bi, off);
        if (ov > bv || (ov == bv && oi < bi)) { bv = ov; bi = oi; }
    }
    int top1 = bi;
    float w0 = (lane == top1)      ? NEG : v0;
    float w1 = (lane + 32 == top1) ? NEG : v1;
    float bv2; int bi2;
    if (w0 >= w1) { bv2 = w0; bi2 = lane; } else { bv2 = w1; bi2 = lane + 32; }
#pragma unroll
    for (int off = 16; off > 0; off >>= 1) {
        float ov = __shfl_xor_sync(0xffffffffu, bv2, off);
        int   oi = __shfl_xor_sync(0xffffffffu, bi2, off);
        if (ov > bv2 || (ov == bv2 && oi < bi2)) { bv2 = ov; bi2 = oi; }
    }
    if (lane == 0) { g_top[bs * 2] = top1; g_top[bs * 2 + 1] = bi2; }
}

// ---------------- register-tiled compressed attention ---------------------------------
__global__ __launch_bounds__(256) void comp_attn_tile_kernel()
{
    extern __shared__ float sm[];
    float* Qt = sm;
    float* Kt = sm + 64 * TS;
    float* Vs = sm + 2 * 64 * TS;
    float* Ps = sm + 3 * 64 * TS;

    const int st = blockIdx.x, h = blockIdx.y, b = blockIdx.z;
    const int tid = threadIdx.x;
    const int ty = tid >> 4, tx = tid & 15;
    const int qbase = st * 64;

    for (int i = tid; i < 4096; i += 256) {
        int r = i >> 6, d = i & 63;
        Qt[d * TS + r] = g_q[((size_t)(b * NS + qbase + r)) * ND + h * 64 + d];
        const size_t gc = ((size_t)(b * 64 + r)) * ND + h * 64 + d;
        Kt[d * TS + r] = g_ck[gc];
        Vs[r * TS + d] = g_cv[gc];
    }
    __syncthreads();

    float s[4][4];
#pragma unroll
    for (int i = 0; i < 4; i++)
#pragma unroll
        for (int j = 0; j < 4; j++) s[i][j] = 0.f;

#pragma unroll 8
    for (int d = 0; d < 64; d++) {
        float4 qv = *(const float4*)&Qt[d * TS + ty * 4];
        float4 kv = *(const float4*)&Kt[d * TS + tx * 4];
        float qa[4] = {qv.x, qv.y, qv.z, qv.w};
        float ka[4] = {kv.x, kv.y, kv.z, kv.w};
#pragma unroll
        for (int i = 0; i < 4; i++)
#pragma unroll
            for (int j = 0; j < 4; j++) s[i][j] += qa[i] * ka[j];
    }
#pragma unroll
    for (int i = 0; i < 4; i++)
#pragma unroll
        for (int j = 0; j < 4; j++)
            Ps[(ty * 4 + i) * PS + tx * 4 + j] = s[i][j] * INVS;
    __syncthreads();

    __shared__ float rowl[64];
    if (tid < 64) {
        float* pr = Ps + tid * PS;
        float m = NEG;
#pragma unroll 8
        for (int c = 0; c < 64; c++) m = fmaxf(m, pr[c]);
        float l = 0.f;
#pragma unroll 8
        for (int c = 0; c < 64; c++) { float p = __expf(pr[c] - m); pr[c] = p; l += p; }
        rowl[tid] = 1.f / l;
    }
    __syncthreads();

    float acc[4][4];
#pragma unroll
    for (int i = 0; i < 4; i++)
#pragma unroll
        for (int j = 0; j < 4; j++) acc[i][j] = 0.f;
#pragma unroll 8
    for (int c = 0; c < 64; c++) {
        float4 vv = *(const float4*)&Vs[c * TS + tx * 4];
        float va[4] = {vv.x, vv.y, vv.z, vv.w};
#pragma unroll
        for (int i = 0; i < 4; i++) {
            float p = Ps[(ty * 4 + i) * PS + c];
#pragma unroll
            for (int j = 0; j < 4; j++) acc[i][j] += p * va[j];
        }
    }
#pragma unroll
    for (int i = 0; i < 4; i++) {
        const float rl = rowl[ty * 4 + i];
        float* orow = g_oc + ((size_t)(b * NS + qbase + ty * 4 + i)) * ND + h * 64 + tx * 4;
        float4 o = make_float4(acc[i][0] * rl, acc[i][1] * rl, acc[i][2] * rl, acc[i][3] * rl);
        *(float4*)orow = o;
    }
}

// ---------------- register-tiled sliding-window attention ------------------------------
__global__ __launch_bounds__(256) void win_attn_kernel()
{
    extern __shared__ float sm[];
    float* Qt = sm;
    float* Kt = sm + 64 * TS;
    float* Vs = sm + 2 * 64 * TS;
    float* Ps = sm + 3 * 64 * TS;

    __shared__ float rowm[64], rowl[64], rowsc[64];

    const int qt = blockIdx.x, h = blockIdx.y, b = blockIdx.z;
    const int tid = threadIdx.x;
    const int ty = tid >> 4, tx = tid & 15;
    const int qbase = qt * 64;

    for (int i = tid; i < 4096; i += 256) {
        int r = i >> 6, d = i & 63;
        Qt[d * TS + r] = g_q[((size_t)(b * NS + qbase + r)) * ND + h * 64 + d];
    }
    if (tid < 64) { rowm[tid] = NEG; rowl[tid] = 0.f; }

    float acc[4][4];
#pragma unroll
    for (int i = 0; i < 4; i++)
#pragma unroll
        for (int j = 0; j < 4; j++) acc[i][j] = 0.f;

    const int kt_lo = (qt >= 4) ? qt - 4 : 0;
    for (int kt = kt_lo; kt <= qt; kt++) {
        const int kbase = kt * 64;
        __syncthreads();
        for (int i = tid; i < 4096; i += 256) {
            int r = i >> 6, d = i & 63;
            const size_t g = ((size_t)(b * NS + kbase + r)) * ND + h * 64 + d;
            Kt[d * TS + r] = g_k[g];
            Vs[r * TS + d] = g_v[g];
        }
        __syncthreads();

        float s[4][4];
#pragma unroll
        for (int i = 0; i < 4; i++)
#pragma unroll
            for (int j = 0; j < 4; j++) s[i][j] = 0.f;
#pragma unroll 8
        for (int d = 0; d < 64; d++) {
            float4 qv = *(const float4*)&Qt[d * TS + ty * 4];
            float4 kv = *(const float4*)&Kt[d * TS + tx * 4];
            float qa[4] = {qv.x, qv.y, qv.z, qv.w};
            float ka[4] = {kv.x, kv.y, kv.z, kv.w};
#pragma unroll
            for (int i = 0; i < 4; i++)
#pragma unroll
                for (int j = 0; j < 4; j++) s[i][j] += qa[i] * ka[j];
        }
#pragma unroll
        for (int i = 0; i < 4; i++) {
            const int qi = qbase + ty * 4 + i;
#pragma unroll
            for (int j = 0; j < 4; j++) {
                const int kj = kbase + tx * 4 + j;
                float v = (kj <= qi && qi - kj <= NWIN) ? s[i][j] * INVS : NEG;
                Ps[(ty * 4 + i) * PS + tx * 4 + j] = v;
            }
        }
        __syncthreads();

        if (tid < 64) {
            float* pr = Ps + tid * PS;
            float m = rowm[tid], mn = m;
#pragma unroll 8
            for (int c = 0; c < 64; c++) mn = fmaxf(mn, pr[c]);
            float sc = __expf(m - mn);
            float l = rowl[tid] * sc;
#pragma unroll 8
            for (int c = 0; c < 64; c++) { float p = __expf(pr[c] - mn); pr[c] = p; l += p; }
            rowm[tid] = mn; rowl[tid] = l; rowsc[tid] = sc;
        }
        __syncthreads();

#pragma unroll
        for (int i = 0; i < 4; i++) {
            const float sc = rowsc[ty * 4 + i];
#pragma unroll
            for (int j = 0; j < 4; j++) acc[i][j] *= sc;
        }
#pragma unroll 8
        for (int c = 0; c < 64; c++) {
            float4 vv = *(const float4*)&Vs[c * TS + tx * 4];
            float va[4] = {vv.x, vv.y, vv.z, vv.w};
#pragma unroll
            for (int i = 0; i < 4; i++) {
                float p = Ps[(ty * 4 + i) * PS + c];
#pragma unroll
                for (int j = 0; j < 4; j++) acc[i][j] += p * va[j];
            }
        }
    }

#pragma unroll
    for (int i = 0; i < 4; i++) {
        const float rl = 1.f / rowl[ty * 4 + i];
        float* orow = g_ow + ((size_t)(b * NS + qbase + ty * 4 + i)) * ND + h * 64 + tx * 4;
        float4 o = make_float4(acc[i][0] * rl, acc[i][1] * rl, acc[i][2] * rl, acc[i][3] * rl);
        *(float4*)orow = o;
    }
}

// ---------------- selected attention ---------------------------------------------------
__global__ __launch_bounds__(512) void sel_attn_kernel()
{
    const int bs = blockIdx.x;
    const int b  = bs >> 10, s = bs & 1023;
    const int tid = threadIdx.x;
    const int h = tid >> 5, lane = tid & 31;

    __shared__ int blk_s[2];
    if (tid < 2) blk_s[tid] = g_top[(tid * NS + s) * 2 + b];
    __syncthreads();

    const float2 q2 = *(const float2*)(g_q + bs * ND + h * 64 + lane * 2);

    float myscore = NEG;
#pragma unroll
    for (int m = 0; m < 16; m++) {
        int j = m >> 3, t = m & 7;
        int tok = blk_s[j] * NCB + t;
        float2 k2 = *(const float2*)(g_k + (j * NS + tok) * ND + h * 64 + lane * 2);
        float p = q2.x * k2.x + q2.y * k2.y;
#pragma unroll
        for (int off = 16; off > 0; off >>= 1)
            p += __shfl_xor_sync(0xffffffffu, p, off);
        p *= INVS;
        if (lane == m) myscore = p;
    }
    float mx = myscore;
#pragma unroll
    for (int off = 16; off > 0; off >>= 1)
        mx = fmaxf(mx, __shfl_xor_sync(0xffffffffu, mx, off));
    float p = __expf(myscore - mx);
    float sum = p;
#pragma unroll
    for (int off = 16; off > 0; off >>= 1)
        sum += __shfl_xor_sync(0xffffffffu, sum, off);
    float rs = 1.f / sum;

    float2 acc = make_float2(0.f, 0.f);
#pragma unroll
    for (int m = 0; m < 16; m++) {
        float pm = __shfl_sync(0xffffffffu, p, m);
        int j = m >> 3, t = m & 7;
        int tok = blk_s[j] * NCB + t;
        float2 v2 = *(const float2*)(g_v + (j * NS + tok) * ND + h * 64 + lane * 2);
        acc.x += pm * v2.x; acc.y += pm * v2.y;
    }
    acc.x *= rs; acc.y *= rs;
    *(float2*)(g_os + bs * ND + h * 64 + lane * 2) = acc;
}

// ---------------- gates -----------------------------------------------------------------
__global__ __launch_bounds__(256) void gate_kernel(
    const float* __restrict__ x, const float* __restrict__ Wg,
    const float* __restrict__ bg)
{
    const int row = blockIdx.x * 8 + (threadIdx.x >> 5);
    const int lane = threadIdx.x & 31;
    const float* xr = x + (size_t)row * ND;
    float a0 = 0.f, a1 = 0.f, a2 = 0.f;
    for (int d = lane; d < ND; d += 32) {
        float xv = xr[d];
        a0 += xv * Wg[d * 3 + 0];
        a1 += xv * Wg[d * 3 + 1];
        a2 += xv * Wg[d * 3 + 2];
    }
#pragma unroll
    for (int off = 16; off > 0; off >>= 1) {
        a0 += __shfl_xor_sync(0xffffffffu, a0, off);
        a1 += __shfl_xor_sync(0xffffffffu, a1, off);
        a2 += __shfl_xor_sync(0xffffffffu, a2, off);
    }
    if (lane == 0) {
        g_gates[row * 3 + 0] = 1.f / (1.f + __expf(-(a0 + bg[0])));
        g_gates[row * 3 + 1] = 1.f / (1.f + __expf(-(a1 + bg[1])));
        g_gates[row * 3 + 2] = 1.f / (1.f + __expf(-(a2 + bg[2])));
    }
}

// ---------------- fused combine + bf16-split --------------------------------------------
__global__ __launch_bounds__(256) void combine_split_kernel()
{
    int idx = (blockIdx.x * 256 + threadIdx.x) * 4;
    int bs = idx >> 10;
    float g0 = g_gates[bs * 3 + 0];
    float g1 = g_gates[bs * 3 + 1];
    float g2 = g_gates[bs * 3 + 2];
    float4 oc = *(const float4*)(g_oc + idx);
    float4 os = *(const float4*)(g_os + idx);
    float4 ow = *(const float4*)(g_ow + idx);
    float v0 = g0 * oc.x + g1 * os.x + g2 * ow.x;
    float v1 = g0 * oc.y + g1 * os.y + g2 * ow.y;
    float v2 = g0 * oc.z + g1 * os.z + g2 * ow.z;
    float v3 = g0 * oc.w + g1 * os.w + g2 * ow.w;
    __nv_bfloat16 h0 = __float2bfloat16(v0), h1 = __float2bfloat16(v1);
    __nv_bfloat16 h2 = __float2bfloat16(v2), h3 = __float2bfloat16(v3);
    *(__nv_bfloat162*)(g_ah + idx)     = __halves2bfloat162(h0, h1);
    *(__nv_bfloat162*)(g_ah + idx + 2) = __halves2bfloat162(h2, h3);
    *(__nv_bfloat162*)(g_al + idx) = __halves2bfloat162(
        __float2bfloat16(v0 - __bfloat162float(h0)),
        __float2bfloat16(v1 - __bfloat162float(h1)));
    *(__nv_bfloat162*)(g_al + idx + 2) = __halves2bfloat162(
        __float2bfloat16(v2 - __bfloat162float(h2)),
        __float2bfloat16(v3 - __bfloat162float(h3)));
}

// ---------------- launcher ---------------------------------------------------------------
extern "C" void kernel_launch(void* const* d_in, const int* in_sizes, int n_in,
                              void* d_out, int out_size)
{
    (void)in_sizes; (void)n_in; (void)out_size;
    const float* x   = (const float*)d_in[0];
    const float* Wq  = (const float*)d_in[1];
    const float* Wk  = (const float*)d_in[2];
    const float* Wv  = (const float*)d_in[3];
    const float* Wo  = (const float*)d_in[4];
    const float* bo  = (const float*)d_in[5];
    const float* Wg  = (const float*)d_in[6];
    const float* bg  = (const float*)d_in[7];
    const float* wkc = (const float*)d_in[8];
    const float* wvc = (const float*)d_in[9];
    const float* wpe = (const float*)d_in[10];
    float* out = (float*)d_out;

    void *pq, *pk, *pv, *pah, *pal, *pwh, *pwl, *pwoh, *pwol;
    void *pxkc, *pxvc, *pck, *pcv, *ptt, *pimp, *ppec, *ppvc, *pttp, *pimpp;
    cudaGetSymbolAddress(&pq,   g_q);
    cudaGetSymbolAddress(&pk,   g_k);
    cudaGetSymbolAddress(&pv,   g_v);
    cudaGetSymbolAddress(&pah,  g_ah);
    cudaGetSymbolAddress(&pal,  g_al);
    cudaGetSymbolAddress(&pwh,  g_wh);
    cudaGetSymbolAddress(&pwl,  g_wl);
    cudaGetSymbolAddress(&pwoh, g_woh);
    cudaGetSymbolAddress(&pwol, g_wol);
    cudaGetSymbolAddress(&pxkc, g_xkc);
    cudaGetSymbolAddress(&pxvc, g_xvc);
    cudaGetSymbolAddress(&pck,  g_ck);
    cudaGetSymbolAddress(&pcv,  g_cv);
    cudaGetSymbolAddress(&ptt,  g_tt);
    cudaGetSymbolAddress(&pimp, g_imp);
    cudaGetSymbolAddress(&ppec, g_pec);
    cudaGetSymbolAddress(&ppvc, g_pvc);
    cudaGetSymbolAddress(&pttp, g_ttp);
    cudaGetSymbolAddress(&pimpp, g_impp);

    const __nv_bfloat16* ah  = (const __nv_bfloat16*)pah;
    const __nv_bfloat16* alo = (const __nv_bfloat16*)pal;
    const int NEL = NB * NS * ND;

    static bool inited = false;
    static cudaStream_t sB, sC;
    static cudaEvent_t e0, e1, eB, eC, eW;
    if (!inited) {
        cudaStreamCreateWithFlags(&sB, cudaStreamNonBlocking);
        cudaStreamCreateWithFlags(&sC, cudaStreamNonBlocking);
        cudaEventCreateWithFlags(&e0, cudaEventDisableTiming);
        cudaEventCreateWithFlags(&e1, cudaEventDisableTiming);
        cudaEventCreateWithFlags(&eB, cudaEventDisableTiming);
        cudaEventCreateWithFlags(&eC, cudaEventDisableTiming);
        cudaEventCreateWithFlags(&eW, cudaEventDisableTiming);
        cudaFuncSetAttribute(mma_gemm3_kernel,
                             cudaFuncAttributeMaxDynamicSharedMemorySize, SMEM_GEMM);
        cudaFuncSetAttribute(win_attn_kernel,
                             cudaFuncAttributeMaxDynamicSharedMemorySize, SMEM_ATT);
        cudaFuncSetAttribute(comp_attn_tile_kernel,
                             cudaFuncAttributeMaxDynamicSharedMemorySize, SMEM_ATT);
        inited = true;
    }

    cudaEventRecord(e0, 0);
    cudaStreamWaitEvent(sB, e0, 0);
    cudaStreamWaitEvent(sC, e0, 0);

    // ---- stream C: QKV weight conversion (parallel with split), then gates + Wo ----
    convert_w3_kernel<<<dim3(32, 32, 3), 256, 0, sC>>>(
        Wq, Wk, Wv, (__nv_bfloat16*)pwh, (__nv_bfloat16*)pwl);
    cudaEventRecord(eW, sC);
    gate_kernel<<<(NB * NS) / 8, 256, 0, sC>>>(x, Wg, bg);
    convert_w1_kernel<<<dim3(32, 32), 256, 0, sC>>>(
        Wo, (__nv_bfloat16*)pwoh, (__nv_bfloat16*)pwol);
    cudaEventRecord(eC, sC);

    // ---- main stream: split x, then QKV GEMM ----
    split_kernel<<<NEL / 1024, 256>>>(x, (__nv_bfloat16*)pah, (__nv_bfloat16*)pal);
    cudaStreamWaitEvent(0, eW, 0);
    mma_gemm3_kernel<<<dim3(24, 16), 256, SMEM_GEMM>>>(
        ah, alo, (const __nv_bfloat16*)pwh, (const __nv_bfloat16*)pwl,
        (float*)pq, (float*)pk, (float*)pv, wpe, 1);
    cudaEventRecord(e1, 0);

    // ---- stream B: exact fp32 top-k chain ----
    xc_kernel<<<(NB * NNC * ND) / 256, 256, 0, sB>>>(x, wkc, wvc);
    pe_comb_kernel<<<ND / 256, 256, 0, sB>>>(wpe, wkc, wvc);
    csgemm_kernel<<<dim3(16, 1, 8), 256, 0, sB>>>(
        (const float*)pxkc, (const float*)pxvc, Wk, Wv);
    reduce_ckcv_kernel<<<(2 * 131072) / 256, 256, 0, sB>>>(
        (const float*)ppec, (const float*)ppvc);
    nt_gemm_kernel<<<dim3(16, 1, 8), 256, 0, sB>>>(
        (const float*)pck, Wq, (float*)pttp, 1024, 64L * 1024, 0L, 64L * 1024);
    reduce4_kernel<<<(NB * 65536) / 256, 256, 0, sB>>>(
        (const float*)pttp, (float*)ptt, 65536);
    nt_gemm_kernel<<<dim3(1, 16, 8), 256, 0, sB>>>(
        x, (const float*)ptt, (float*)pimpp, 64, 1024L * 1024, 64L * 1024, 1024L * 64);
    reduce4_kernel<<<(NB * 65536) / 256, 256, 0, sB>>>(
        (const float*)pimpp, (float*)pimp, 65536);
    top2_kernel<<<(NB * NS) / 8, 256, 0, sB>>>();
    cudaStreamWaitEvent(sB, e1, 0);
    comp_attn_tile_kernel<<<dim3(16, 16, 2), 256, SMEM_ATT, sB>>>();
    sel_attn_kernel<<<NB * NS, 512, 0, sB>>>();
    cudaEventRecord(eB, sB);

    // ---- main: window attention, join, fused combine+split, OUT GEMM ----
    win_attn_kernel<<<dim3(NS / 64, NH, NB), 256, SMEM_ATT>>>();
    cudaStreamWaitEvent(0, eB, 0);
    cudaStreamWaitEvent(0, eC, 0);
    combine_split_kernel<<<NEL / 1024, 256>>>();
    mma_gemm3_kernel<<<dim3(8, 16), 256, SMEM_GEMM>>>(
        ah, alo, (const __nv_bfloat16*)pwoh, (const __nv_bfloat16*)pwol,
        out, out, out, bo, 0);
}

// round 17
// speedup vs baseline: 1.1135x; 1.1135x over previous
#include <cuda_runtime.h>
#include <cuda_bf16.h>
#include <cstdint>

#define NB   2
#define NS   1024
#define ND   1024
#define NH   16
#define NHD  64
#define NNC  64
#define NCB  16
#define NSB  8
#define NJ   2
#define NWIN 256

#define INVS 0.125f
#define NEG  (-1e30f)

#define KA   1024
#define BM   128
#define BN   128
#define BK   32
#define AST  40
#define NIT3 96
#define STAGE_BYTES ((BM + BN) * AST * 2)
#define SMEM_GEMM   (4 * STAGE_BYTES)

#define TS   68
#define PS   65
#define SMEM_ATT ((3 * 64 * TS + 64 * PS) * 4)

// ---------------- scratch ----------------
__device__ __align__(16) float g_q [NB*NS*ND];
__device__ __align__(16) float g_k [NB*NS*ND];
__device__ __align__(16) float g_v [NB*NS*ND];
__device__ __align__(16) float g_ck[NB*NNC*ND];
__device__ __align__(16) float g_cv[NB*NNC*ND];
__device__ __align__(16) float g_oc[NB*NS*ND];
__device__ __align__(16) float g_os[NB*NS*ND];
__device__ __align__(16) float g_ow[NB*NS*ND];
__device__ int   g_top[NB*NS*NJ];
__device__ __align__(16) float g_gates[NB*NS*3];
__device__ __align__(16) __nv_bfloat16 g_ah[(size_t)NB*NS*ND];
__device__ __align__(16) __nv_bfloat16 g_al[(size_t)NB*NS*ND];
__device__ __align__(16) __nv_bfloat16 g_wh[(size_t)3*ND*ND];
__device__ __align__(16) __nv_bfloat16 g_wl[(size_t)3*ND*ND];
__device__ __align__(16) __nv_bfloat16 g_woh[(size_t)ND*ND];
__device__ __align__(16) __nv_bfloat16 g_wol[(size_t)ND*ND];
__device__ __align__(16) float g_xkc[NB*NNC*ND];
__device__ __align__(16) float g_xvc[NB*NNC*ND];
__device__ __align__(16) float g_pec[ND];
__device__ __align__(16) float g_pvc[ND];
__device__ __align__(16) float g_tt [NB*NNC*ND];
__device__ __align__(16) float g_imp[NB*NS*NNC];
__device__ __align__(16) float g_cp  [2*4*128*1024];
__device__ __align__(16) float g_ttp [2*4*64*1024];
__device__ __align__(16) float g_impp[2*4*1024*64];

// ======================= PTX helpers ================================================
__device__ __forceinline__ void cp16(uint32_t d, const void* s) {
    asm volatile("cp.async.cg.shared.global [%0], [%1], 16;" :: "r"(d), "l"(s));
}
__device__ __forceinline__ void cp_commit() {
    asm volatile("cp.async.commit_group;");
}
__device__ __forceinline__ void cp_wait1() {
    asm volatile("cp.async.wait_group 1;");
}
__device__ __forceinline__ void cp_wait2() {
    asm volatile("cp.async.wait_group 2;");
}
__device__ __forceinline__ void ldsm_x4(uint32_t& r0, uint32_t& r1, uint32_t& r2, uint32_t& r3,
                                        uint32_t addr) {
    asm volatile("ldmatrix.sync.aligned.m8n8.x4.shared.b16 {%0,%1,%2,%3}, [%4];"
        : "=r"(r0), "=r"(r1), "=r"(r2), "=r"(r3) : "r"(addr));
}
__device__ __forceinline__ void mma16816(float* c, const uint32_t* a, const uint32_t* b) {
    asm volatile("mma.sync.aligned.m16n8k16.row.col.f32.bf16.bf16.f32 "
        "{%0,%1,%2,%3}, {%4,%5,%6,%7}, {%8,%9}, {%0,%1,%2,%3};"
        : "+f"(c[0]), "+f"(c[1]), "+f"(c[2]), "+f"(c[3])
        : "r"(a[0]), "r"(a[1]), "r"(a[2]), "r"(a[3]), "r"(b[0]), "r"(b[1]));
}

// ======================= split conversions =========================================
__global__ __launch_bounds__(256) void split_kernel(
    const float* __restrict__ src, __nv_bfloat16* __restrict__ hi,
    __nv_bfloat16* __restrict__ lo)
{
    int idx = (blockIdx.x * 256 + threadIdx.x) * 4;
    float4 v = *(const float4*)(src + idx);
    __nv_bfloat16 h0 = __float2bfloat16(v.x), h1 = __float2bfloat16(v.y);
    __nv_bfloat16 h2 = __float2bfloat16(v.z), h3 = __float2bfloat16(v.w);
    *(__nv_bfloat162*)(hi + idx)     = __halves2bfloat162(h0, h1);
    *(__nv_bfloat162*)(hi + idx + 2) = __halves2bfloat162(h2, h3);
    *(__nv_bfloat162*)(lo + idx) = __halves2bfloat162(
        __float2bfloat16(v.x - __bfloat162float(h0)),
        __float2bfloat16(v.y - __bfloat162float(h1)));
    *(__nv_bfloat162*)(lo + idx + 2) = __halves2bfloat162(
        __float2bfloat16(v.z - __bfloat162float(h2)),
        __float2bfloat16(v.w - __bfloat162float(h3)));
}

__global__ __launch_bounds__(256) void convert_w3_kernel(
    const float* __restrict__ W0, const float* __restrict__ W1,
    const float* __restrict__ W2,
    __nv_bfloat16* __restrict__ Wh, __nv_bfloat16* __restrict__ Wl)
{
    const int z = blockIdx.z;
    const float* W = (z == 0) ? W0 : (z == 1) ? W1 : W2;
    const int row_off = z * 1024;

    __shared__ float t[32][33];
    int n0 = blockIdx.x * 32, k0 = blockIdx.y * 32;
    int tx = threadIdx.x & 31, ty = threadIdx.x >> 5;
#pragma unroll
    for (int i = 0; i < 32; i += 8)
        t[ty + i][tx] = W[(k0 + ty + i) * 1024 + n0 + tx];
    __syncthreads();
#pragma unroll
    for (int i = 0; i < 32; i += 8) {
        int n = row_off + n0 + ty + i, k = k0 + tx;
        float v = t[tx][ty + i];
        __nv_bfloat16 h = __float2bfloat16(v);
        Wh[(size_t)n * 1024 + k] = h;
        Wl[(size_t)n * 1024 + k] = __float2bfloat16(v - __bfloat162float(h));
    }
}

__global__ __launch_bounds__(256) void convert_w1_kernel(
    const float* __restrict__ W,
    __nv_bfloat16* __restrict__ Wh, __nv_bfloat16* __restrict__ Wl)
{
    __shared__ float t[32][33];
    int n0 = blockIdx.x * 32, k0 = blockIdx.y * 32;
    int tx = threadIdx.x & 31, ty = threadIdx.x >> 5;
#pragma unroll
    for (int i = 0; i < 32; i += 8)
        t[ty + i][tx] = W[(k0 + ty + i) * 1024 + n0 + tx];
    __syncthreads();
#pragma unroll
    for (int i = 0; i < 32; i += 8) {
        int n = n0 + ty + i, k = k0 + tx;
        float v = t[tx][ty + i];
        __nv_bfloat16 h = __float2bfloat16(v);
        Wh[(size_t)n * 1024 + k] = h;
        Wl[(size_t)n * 1024 + k] = __float2bfloat16(v - __bfloat162float(h));
    }
}

// ======================= fused 3-term HMMA GEMM (4-stage, reg double-buffered) ======
__global__ void __launch_bounds__(256) mma_gemm3_kernel(
    const __nv_bfloat16* __restrict__ Ah, const __nv_bfloat16* __restrict__ Al,
    const __nv_bfloat16* __restrict__ Wh, const __nv_bfloat16* __restrict__ Wl,
    float* __restrict__ Cq, float* __restrict__ Ck, float* __restrict__ Cv,
    const float* __restrict__ extra, int qkv_mode)
{
    extern __shared__ __nv_bfloat16 smem[];

    const int tid = threadIdx.x;
    const int wid = tid >> 5, lane = tid & 31;
    const int wm = wid >> 2, wn = wid & 3;
    const int mt = blockIdx.y * BM, nt = blockIdx.x * BN;

    const uint32_t sb = (uint32_t)__cvta_generic_to_shared(smem);
    const uint32_t B_OFF = BM * AST * 2;

    const int lrow = tid >> 1;
    const int lc   = (tid & 1) * 2;
    const size_t aoff = (size_t)(mt + lrow) * KA + lc * 8;
    const size_t boff = (size_t)(nt + lrow) * KA + lc * 8;
    const __nv_bfloat16* aSrc[2] = {Ah + aoff, Al + aoff};
    const __nv_bfloat16* bSrc[2] = {Wh + boff, Wl + boff};
    const uint32_t dA = sb + (lrow * AST + lc * 8) * 2;
    const uint32_t dB = sb + B_OFF + (lrow * AST + lc * 8) * 2;

    float c[4][4][4];
#pragma unroll
    for (int i = 0; i < 4; i++)
#pragma unroll
        for (int j = 0; j < 4; j++)
#pragma unroll
            for (int r = 0; r < 4; r++) c[i][j][r] = 0.f;

    const int al  = lane & 15;
    const int ahi = lane >> 4;

    // double-buffered fragment registers (F0 = even half-step, F1 = odd)
    uint32_t a0[4][4], b0[4][2], a1[4][4], b1[4][2];

#define ISSUE(j) do {                                                       \
        const int t_  = (j) >> 5;                                           \
        const int k0_ = ((j) & 31) * BK;                                    \
        const __nv_bfloat16* ga_ = aSrc[t_ == 2 ? 1 : 0] + k0_;             \
        const __nv_bfloat16* gb_ = bSrc[t_ == 1 ? 1 : 0] + k0_;             \
        const uint32_t so_ = ((j) & 3) * STAGE_BYTES;                       \
        cp16(dA + so_, ga_);       cp16(dA + so_ + 16, ga_ + 8);            \
        cp16(dB + so_, gb_);       cp16(dB + so_ + 16, gb_ + 8);            \
    } while (0)

#define LOADF(A_, B_, sA_, sB_, kg_) do {                                   \
        _Pragma("unroll")                                                   \
        for (int i_ = 0; i_ < 4; i_++) {                                    \
            uint32_t ad_ = (sA_) + ((wm * 64 + i_ * 16 + al) * AST + (kg_) * 8) * 2; \
            ldsm_x4(A_[i_][0], A_[i_][1], A_[i_][2], A_[i_][3], ad_);       \
        }                                                                   \
        _Pragma("unroll")                                                   \
        for (int jj_ = 0; jj_ < 2; jj_++) {                                 \
            uint32_t bd_ = (sB_) + ((wn * 32 + jj_ * 16 + al) * AST + (kg_) * 8) * 2; \
            uint32_t r0_, r1_, r2_, r3_;                                    \
            ldsm_x4(r0_, r1_, r2_, r3_, bd_);                               \
            B_[jj_ * 2 + 0][0] = r0_; B_[jj_ * 2 + 1][0] = r1_;             \
            B_[jj_ * 2 + 0][1] = r2_; B_[jj_ * 2 + 1][1] = r3_;             \
        }                                                                   \
    } while (0)

#define MMAF(A_, B_) do {                                                   \
        _Pragma("unroll")                                                   \
        for (int i_ = 0; i_ < 4; i_++)                                      \
            _Pragma("unroll")                                               \
            for (int j_ = 0; j_ < 4; j_++) mma16816(c[i_][j_], A_[i_], B_[j_]); \
    } while (0)

    ISSUE(0); cp_commit();
    ISSUE(1); cp_commit();
    ISSUE(2); cp_commit();

    // prologue: slot 0 ready, preload (it=0, ks=0) fragments
    cp_wait2();
    __syncthreads();
    LOADF(a0, b0, sb, sb + B_OFF, ahi);

    for (int it = 0; it < NIT3; it++) {
        cp_wait1();                        // slots it and it+1 both resident
        __syncthreads();
        if (it + 3 < NIT3) ISSUE(it + 3);
        cp_commit();

        const uint32_t sA  = sb + (it & 3) * STAGE_BYTES;
        const uint32_t sB  = sA + B_OFF;
        const uint32_t sAn = sb + ((it + 1) & 3) * STAGE_BYTES;
        const uint32_t sBn = sAn + B_OFF;

        LOADF(a1, b1, sA, sB, 2 + ahi);    // (it, ks=1) frags
        MMAF(a0, b0);                      // ks=0 MMAs (overlap ldsm above)
        if (it + 1 < NIT3)
            LOADF(a0, b0, sAn, sBn, ahi);  // (it+1, ks=0) frags — cross-iter prefetch
        MMAF(a1, b1);                      // ks=1 MMAs
    }
#undef ISSUE
#undef LOADF
#undef MMAF

    float* dst;
    bool add_pe = false;
    int ncol0;
    if (qkv_mode) {
        const int seg = nt >> 10;
        dst = (seg == 0) ? Cq : (seg == 1 ? Ck : Cv);
        add_pe = (seg != 0);
        ncol0 = nt & 1023;
    } else {
        dst = Cq;
        ncol0 = nt;
    }

    const int mbase = mt + wm * 64;
    const int nbase = ncol0 + wn * 32;
    const int rr = lane >> 2, cc = (lane & 3) * 2;
#pragma unroll
    for (int i = 0; i < 4; i++) {
#pragma unroll
        for (int j = 0; j < 4; j++) {
            int row = mbase + i * 16 + rr;
            int col = nbase + j * 8 + cc;
            float2 v0 = make_float2(c[i][j][0], c[i][j][1]);
            float2 v1 = make_float2(c[i][j][2], c[i][j][3]);
            if (qkv_mode) {
                if (add_pe) {
                    const float* p0 = extra + (row & 15) * 1024 + col;
                    const float* p1 = extra + ((row + 8) & 15) * 1024 + col;
                    v0.x += p0[0]; v0.y += p0[1];
                    v1.x += p1[0]; v1.y += p1[1];
                }
            } else {
                v0.x += extra[col]; v0.y += extra[col + 1];
                v1.x += extra[col]; v1.y += extra[col + 1];
            }
            *(float2*)(dst + (size_t)row * 1024 + col)       = v0;
            *(float2*)(dst + (size_t)(row + 8) * 1024 + col) = v1;
        }
    }
}

// ======================= fp32 SGEMM, K-split x4 (ck/cv partials) ====================
__global__ __launch_bounds__(256) void csgemm_kernel(
    const float* __restrict__ Ak, const float* __restrict__ Av,
    const float* __restrict__ Wk, const float* __restrict__ Wv)
{
    const int path = blockIdx.z >> 2, kc = blockIdx.z & 3;
    const float* A  = path ? Av : Ak;
    const float* Bm = path ? Wv : Wk;
    float* C = g_cp + (size_t)blockIdx.z * (128 * 1024);

    __shared__ float As[16][132];
    __shared__ float Bs[16][64];

    const int tid = threadIdx.x;
    const int bn  = blockIdx.x * 64;
    const int tx  = tid & 15;
    const int ty  = tid >> 4;

    const int arow = tid >> 1;
    const int acol = (tid & 1) * 8;
    const int brow = tid >> 4;
    const int bcol = (tid & 15) * 4;

    float acc[8][4];
#pragma unroll
    for (int i = 0; i < 8; i++)
#pragma unroll
        for (int j = 0; j < 4; j++) acc[i][j] = 0.f;

    const int kbeg = kc * 256, kend = kbeg + 256;
    for (int k0 = kbeg; k0 < kend; k0 += 16) {
        float4 a0 = *(const float4*)(A + arow * 1024 + k0 + acol);
        float4 a1 = *(const float4*)(A + arow * 1024 + k0 + acol + 4);
        As[acol+0][arow] = a0.x; As[acol+1][arow] = a0.y;
        As[acol+2][arow] = a0.z; As[acol+3][arow] = a0.w;
        As[acol+4][arow] = a1.x; As[acol+5][arow] = a1.y;
        As[acol+6][arow] = a1.z; As[acol+7][arow] = a1.w;
        float4 b4 = *(const float4*)(Bm + (k0 + brow) * 1024 + bn + bcol);
        *(float4*)&Bs[brow][bcol] = b4;
        __syncthreads();

#pragma unroll
        for (int kk = 0; kk < 16; kk++) {
            float4 t0 = *(const float4*)&As[kk][ty * 8];
            float4 t1 = *(const float4*)&As[kk][ty * 8 + 4];
            float4 bb = *(const float4*)&Bs[kk][tx * 4];
            float ar[8] = {t0.x, t0.y, t0.z, t0.w, t1.x, t1.y, t1.z, t1.w};
            float br[4] = {bb.x, bb.y, bb.z, bb.w};
#pragma unroll
            for (int i = 0; i < 8; i++)
#pragma unroll
                for (int j = 0; j < 4; j++) acc[i][j] += ar[i] * br[j];
        }
        __syncthreads();
    }

#pragma unroll
    for (int i = 0; i < 8; i++) {
        int m = ty * 8 + i;
#pragma unroll
        for (int j = 0; j < 4; j++)
            C[m * 1024 + bn + tx * 4 + j] = acc[i][j];
    }
}

__global__ __launch_bounds__(256) void reduce_ckcv_kernel(
    const float* __restrict__ bk, const float* __restrict__ bv)
{
    int idx = blockIdx.x * 256 + threadIdx.x;
    int path = idx >> 17, off = idx & 131071;
    const float* P = g_cp + (size_t)path * 4 * 131072;
    float s = P[off] + P[131072 + off] + P[2 * 131072 + off] + P[3 * 131072 + off];
    s += (path ? bv : bk)[off & 1023];
    (path ? g_cv : g_ck)[off] = s;
}

// ======================= fp32 NT GEMM, K-split x4 ===================================
__global__ __launch_bounds__(256) void nt_gemm_kernel(
    const float* __restrict__ A, const float* __restrict__ B, float* __restrict__ C,
    int N, long aB, long bB, long cB)
{
    const int b = blockIdx.z >> 2, kc = blockIdx.z & 3;
    const float* Ab = A + (size_t)b * aB;
    const float* Bb = B + (size_t)b * bB;
    float* Cb = C + (size_t)blockIdx.z * cB;

    __shared__ float As[64][33];
    __shared__ float Bs[64][33];

    const int tid = threadIdx.x;
    const int row = tid >> 2;
    const int c4  = (tid & 3) * 8;
    const int ty = tid >> 4, tx = tid & 15;
    const int i0 = blockIdx.y * 64, j0 = blockIdx.x * 64;

    float acc[4][4];
#pragma unroll
    for (int i = 0; i < 4; i++)
#pragma unroll
        for (int j = 0; j < 4; j++) acc[i][j] = 0.f;

    const int kbeg = kc * 256, kend = kbeg + 256;
    for (int k0 = kbeg; k0 < kend; k0 += 32) {
        float4 a0 = *(const float4*)(Ab + (size_t)(i0 + row) * 1024 + k0 + c4);
        float4 a1 = *(const float4*)(Ab + (size_t)(i0 + row) * 1024 + k0 + c4 + 4);
        As[row][c4+0] = a0.x; As[row][c4+1] = a0.y;
        As[row][c4+2] = a0.z; As[row][c4+3] = a0.w;
        As[row][c4+4] = a1.x; As[row][c4+5] = a1.y;
        As[row][c4+6] = a1.z; As[row][c4+7] = a1.w;
        float4 b0 = *(const float4*)(Bb + (size_t)(j0 + row) * 1024 + k0 + c4);
        float4 b1 = *(const float4*)(Bb + (size_t)(j0 + row) * 1024 + k0 + c4 + 4);
        Bs[row][c4+0] = b0.x; Bs[row][c4+1] = b0.y;
        Bs[row][c4+2] = b0.z; Bs[row][c4+3] = b0.w;
        Bs[row][c4+4] = b1.x; Bs[row][c4+5] = b1.y;
        Bs[row][c4+6] = b1.z; Bs[row][c4+7] = b1.w;
        __syncthreads();

#pragma unroll 8
        for (int k = 0; k < 32; k++) {
            float ar[4], br[4];
#pragma unroll
            for (int i = 0; i < 4; i++) ar[i] = As[ty * 4 + i][k];
#pragma unroll
            for (int j = 0; j < 4; j++) br[j] = Bs[tx * 4 + j][k];
#pragma unroll
            for (int i = 0; i < 4; i++)
#pragma unroll
                for (int j = 0; j < 4; j++) acc[i][j] += ar[i] * br[j];
        }
        __syncthreads();
    }

#pragma unroll
    for (int i = 0; i < 4; i++)
#pragma unroll
        for (int j = 0; j < 4; j++)
            Cb[(size_t)(i0 + ty * 4 + i) * N + j0 + tx * 4 + j] = acc[i][j];
}

__global__ __launch_bounds__(256) void reduce4_kernel(
    const float* __restrict__ P, float* __restrict__ out, int n)
{
    int idx = blockIdx.x * 256 + threadIdx.x;
    int b = idx / n, off = idx - b * n;
    const float* Pb = P + (size_t)b * 4 * n;
    out[idx] = Pb[off] + Pb[n + off] + Pb[2 * n + off] + Pb[3 * n + off];
}

// ---------------- exact compressed-row inputs ---------------------------------------
__global__ __launch_bounds__(256) void xc_kernel(
    const float* __restrict__ x, const float* __restrict__ wkc,
    const float* __restrict__ wvc)
{
    int idx = blockIdx.x * 256 + threadIdx.x;
    int d = idx & 1023;
    int n = (idx >> 10) & 63;
    int b = idx >> 16;
    const float* xb = x + ((size_t)(b * NS + n * NCB)) * ND + d;
    float sk = 0.f, sv = 0.f;
#pragma unroll
    for (int t = 0; t < NCB; t++) {
        float xv = xb[t * ND];
        sk += wkc[t] * xv;
        sv += wvc[t] * xv;
    }
    g_xkc[idx] = sk;
    g_xvc[idx] = sv;
}

__global__ __launch_bounds__(256) void pe_comb_kernel(
    const float* __restrict__ wpe, const float* __restrict__ wkc,
    const float* __restrict__ wvc)
{
    int d = blockIdx.x * 256 + threadIdx.x;
    float sk = 0.f, sv = 0.f;
#pragma unroll
    for (int t = 0; t < NCB; t++) {
        float p = wpe[t * ND + d];
        sk += wkc[t] * p;
        sv += wvc[t] * p;
    }
    g_pec[d] = sk;
    g_pvc[d] = sv;
}

// ---------------- top-2 ---------------------------------------------------------------
__global__ __launch_bounds__(256) void top2_kernel()
{
    const int bs = blockIdx.x * 8 + (threadIdx.x >> 5);
    const int lane = threadIdx.x & 31;
    const float* row = g_imp + (size_t)bs * 64;
    float v0 = row[lane], v1 = row[lane + 32];

    float bv; int bi;
    if (v0 >= v1) { bv = v0; bi = lane; } else { bv = v1; bi = lane + 32; }
#pragma unroll
    for (int off = 16; off > 0; off >>= 1) {
        float ov = __shfl_xor_sync(0xffffffffu, bv, off);
        int   oi = __shfl_xor_sync(0xffffffffu, bi, off);
        if (ov > bv || (ov == bv && oi < bi)) { bv = ov; bi = oi; }
    }
    int top1 = bi;
    float w0 = (lane == top1)      ? NEG : v0;
    float w1 = (lane + 32 == top1) ? NEG : v1;
    float bv2; int bi2;
    if (w0 >= w1) { bv2 = w0; bi2 = lane; } else { bv2 = w1; bi2 = lane + 32; }
#pragma unroll
    for (int off = 16; off > 0; off >>= 1) {
        float ov = __shfl_xor_sync(0xffffffffu, bv2, off);
        int   oi = __shfl_xor_sync(0xffffffffu, bi2, off);
        if (ov > bv2 || (ov == bv2 && oi < bi2)) { bv2 = ov; bi2 = oi; }
    }
    if (lane == 0) { g_top[bs * 2] = top1; g_top[bs * 2 + 1] = bi2; }
}

// ---------------- register-tiled compressed attention ---------------------------------
__global__ __launch_bounds__(256) void comp_attn_tile_kernel()
{
    extern __shared__ float sm[];
    float* Qt = sm;
    float* Kt = sm + 64 * TS;
    float* Vs = sm + 2 * 64 * TS;
    float* Ps = sm + 3 * 64 * TS;

    const int st = blockIdx.x, h = blockIdx.y, b = blockIdx.z;
    const int tid = threadIdx.x;
    const int ty = tid >> 4, tx = tid & 15;
    const int qbase = st * 64;

    for (int i = tid; i < 4096; i += 256) {
        int r = i >> 6, d = i & 63;
        Qt[d * TS + r] = g_q[((size_t)(b * NS + qbase + r)) * ND + h * 64 + d];
        const size_t gc = ((size_t)(b * 64 + r)) * ND + h * 64 + d;
        Kt[d * TS + r] = g_ck[gc];
        Vs[r * TS + d] = g_cv[gc];
    }
    __syncthreads();

    float s[4][4];
#pragma unroll
    for (int i = 0; i < 4; i++)
#pragma unroll
        for (int j = 0; j < 4; j++) s[i][j] = 0.f;

#pragma unroll 8
    for (int d = 0; d < 64; d++) {
        float4 qv = *(const float4*)&Qt[d * TS + ty * 4];
        float4 kv = *(const float4*)&Kt[d * TS + tx * 4];
        float qa[4] = {qv.x, qv.y, qv.z, qv.w};
        float ka[4] = {kv.x, kv.y, kv.z, kv.w};
#pragma unroll
        for (int i = 0; i < 4; i++)
#pragma unroll
            for (int j = 0; j < 4; j++) s[i][j] += qa[i] * ka[j];
    }
#pragma unroll
    for (int i = 0; i < 4; i++)
#pragma unroll
        for (int j = 0; j < 4; j++)
            Ps[(ty * 4 + i) * PS + tx * 4 + j] = s[i][j] * INVS;
    __syncthreads();

    __shared__ float rowl[64];
    if (tid < 64) {
        float* pr = Ps + tid * PS;
        float m = NEG;
#pragma unroll 8
        for (int c = 0; c < 64; c++) m = fmaxf(m, pr[c]);
        float l = 0.f;
#pragma unroll 8
        for (int c = 0; c < 64; c++) { float p = __expf(pr[c] - m); pr[c] = p; l += p; }
        rowl[tid] = 1.f / l;
    }
    __syncthreads();

    float acc[4][4];
#pragma unroll
    for (int i = 0; i < 4; i++)
#pragma unroll
        for (int j = 0; j < 4; j++) acc[i][j] = 0.f;
#pragma unroll 8
    for (int c = 0; c < 64; c++) {
        float4 vv = *(const float4*)&Vs[c * TS + tx * 4];
        float va[4] = {vv.x, vv.y, vv.z, vv.w};
#pragma unroll
        for (int i = 0; i < 4; i++) {
            float p = Ps[(ty * 4 + i) * PS + c];
#pragma unroll
            for (int j = 0; j < 4; j++) acc[i][j] += p * va[j];
        }
    }
#pragma unroll
    for (int i = 0; i < 4; i++) {
        const float rl = rowl[ty * 4 + i];
        float* orow = g_oc + ((size_t)(b * NS + qbase + ty * 4 + i)) * ND + h * 64 + tx * 4;
        float4 o = make_float4(acc[i][0] * rl, acc[i][1] * rl, acc[i][2] * rl, acc[i][3] * rl);
        *(float4*)orow = o;
    }
}

// ---------------- register-tiled sliding-window attention ------------------------------
__global__ __launch_bounds__(256) void win_attn_kernel()
{
    extern __shared__ float sm[];
    float* Qt = sm;
    float* Kt = sm + 64 * TS;
    float* Vs = sm + 2 * 64 * TS;
    float* Ps = sm + 3 * 64 * TS;

    __shared__ float rowm[64], rowl[64], rowsc[64];

    const int qt = blockIdx.x, h = blockIdx.y, b = blockIdx.z;
    const int tid = threadIdx.x;
    const int ty = tid >> 4, tx = tid & 15;
    const int qbase = qt * 64;

    for (int i = tid; i < 4096; i += 256) {
        int r = i >> 6, d = i & 63;
        Qt[d * TS + r] = g_q[((size_t)(b * NS + qbase + r)) * ND + h * 64 + d];
    }
    if (tid < 64) { rowm[tid] = NEG; rowl[tid] = 0.f; }

    float acc[4][4];
#pragma unroll
    for (int i = 0; i < 4; i++)
#pragma unroll
        for (int j = 0; j < 4; j++) acc[i][j] = 0.f;

    const int kt_lo = (qt >= 4) ? qt - 4 : 0;
    for (int kt = kt_lo; kt <= qt; kt++) {
        const int kbase = kt * 64;
        __syncthreads();
        for (int i = tid; i < 4096; i += 256) {
            int r = i >> 6, d = i & 63;
            const size_t g = ((size_t)(b * NS + kbase + r)) * ND + h * 64 + d;
            Kt[d * TS + r] = g_k[g];
            Vs[r * TS + d] = g_v[g];
        }
        __syncthreads();

        float s[4][4];
#pragma unroll
        for (int i = 0; i < 4; i++)
#pragma unroll
            for (int j = 0; j < 4; j++) s[i][j] = 0.f;
#pragma unroll 8
        for (int d = 0; d < 64; d++) {
            float4 qv = *(const float4*)&Qt[d * TS + ty * 4];
            float4 kv = *(const float4*)&Kt[d * TS + tx * 4];
            float qa[4] = {qv.x, qv.y, qv.z, qv.w};
            float ka[4] = {kv.x, kv.y, kv.z, kv.w};
#pragma unroll
            for (int i = 0; i < 4; i++)
#pragma unroll
                for (int j = 0; j < 4; j++) s[i][j] += qa[i] * ka[j];
        }
#pragma unroll
        for (int i = 0; i < 4; i++) {
            const int qi = qbase + ty * 4 + i;
#pragma unroll
            for (int j = 0; j < 4; j++) {
                const int kj = kbase + tx * 4 + j;
                float v = (kj <= qi && qi - kj <= NWIN) ? s[i][j] * INVS : NEG;
                Ps[(ty * 4 + i) * PS + tx * 4 + j] = v;
            }
        }
        __syncthreads();

        if (tid < 64) {
            float* pr = Ps + tid * PS;
            float m = rowm[tid], mn = m;
#pragma unroll 8
            for (int c = 0; c < 64; c++) mn = fmaxf(mn, pr[c]);
            float sc = __expf(m - mn);
            float l = rowl[tid] * sc;
#pragma unroll 8
            for (int c = 0; c < 64; c++) { float p = __expf(pr[c] - mn); pr[c] = p; l += p; }
            rowm[tid] = mn; rowl[tid] = l; rowsc[tid] = sc;
        }
        __syncthreads();

#pragma unroll
        for (int i = 0; i < 4; i++) {
            const float sc = rowsc[ty * 4 + i];
#pragma unroll
            for (int j = 0; j < 4; j++) acc[i][j] *= sc;
        }
#pragma unroll 8
        for (int c = 0; c < 64; c++) {
            float4 vv = *(const float4*)&Vs[c * TS + tx * 4];
            float va[4] = {vv.x, vv.y, vv.z, vv.w};
#pragma unroll
            for (int i = 0; i < 4; i++) {
                float p = Ps[(ty * 4 + i) * PS + c];
#pragma unroll
                for (int j = 0; j < 4; j++) acc[i][j] += p * va[j];
            }
        }
    }

#pragma unroll
    for (int i = 0; i < 4; i++) {
        const float rl = 1.f / rowl[ty * 4 + i];
        float* orow = g_ow + ((size_t)(b * NS + qbase + ty * 4 + i)) * ND + h * 64 + tx * 4;
        float4 o = make_float4(acc[i][0] * rl, acc[i][1] * rl, acc[i][2] * rl, acc[i][3] * rl);
        *(float4*)orow = o;
    }
}

// ---------------- selected attention ---------------------------------------------------
__global__ __launch_bounds__(512) void sel_attn_kernel()
{
    const int bs = blockIdx.x;
    const int b  = bs >> 10, s = bs & 1023;
    const int tid = threadIdx.x;
    const int h = tid >> 5, lane = tid & 31;

    __shared__ int blk_s[2];
    if (tid < 2) blk_s[tid] = g_top[(tid * NS + s) * 2 + b];
    __syncthreads();

    const float2 q2 = *(const float2*)(g_q + bs * ND + h * 64 + lane * 2);

    float myscore = NEG;
#pragma unroll
    for (int m = 0; m < 16; m++) {
        int j = m >> 3, t = m & 7;
        int tok = blk_s[j] * NCB + t;
        float2 k2 = *(const float2*)(g_k + (j * NS + tok) * ND + h * 64 + lane * 2);
        float p = q2.x * k2.x + q2.y * k2.y;
#pragma unroll
        for (int off = 16; off > 0; off >>= 1)
            p += __shfl_xor_sync(0xffffffffu, p, off);
        p *= INVS;
        if (lane == m) myscore = p;
    }
    float mx = myscore;
#pragma unroll
    for (int off = 16; off > 0; off >>= 1)
        mx = fmaxf(mx, __shfl_xor_sync(0xffffffffu, mx, off));
    float p = __expf(myscore - mx);
    float sum = p;
#pragma unroll
    for (int off = 16; off > 0; off >>= 1)
        sum += __shfl_xor_sync(0xffffffffu, sum, off);
    float rs = 1.f / sum;

    float2 acc = make_float2(0.f, 0.f);
#pragma unroll
    for (int m = 0; m < 16; m++) {
        float pm = __shfl_sync(0xffffffffu, p, m);
        int j = m >> 3, t = m & 7;
        int tok = blk_s[j] * NCB + t;
        float2 v2 = *(const float2*)(g_v + (j * NS + tok) * ND + h * 64 + lane * 2);
        acc.x += pm * v2.x; acc.y += pm * v2.y;
    }
    acc.x *= rs; acc.y *= rs;
    *(float2*)(g_os + bs * ND + h * 64 + lane * 2) = acc;
}

// ---------------- gates -----------------------------------------------------------------
__global__ __launch_bounds__(256) void gate_kernel(
    const float* __restrict__ x, const float* __restrict__ Wg,
    const float* __restrict__ bg)
{
    const int row = blockIdx.x * 8 + (threadIdx.x >> 5);
    const int lane = threadIdx.x & 31;
    const float* xr = x + (size_t)row * ND;
    float a0 = 0.f, a1 = 0.f, a2 = 0.f;
    for (int d = lane; d < ND; d += 32) {
        float xv = xr[d];
        a0 += xv * Wg[d * 3 + 0];
        a1 += xv * Wg[d * 3 + 1];
        a2 += xv * Wg[d * 3 + 2];
    }
#pragma unroll
    for (int off = 16; off > 0; off >>= 1) {
        a0 += __shfl_xor_sync(0xffffffffu, a0, off);
        a1 += __shfl_xor_sync(0xffffffffu, a1, off);
        a2 += __shfl_xor_sync(0xffffffffu, a2, off);
    }
    if (lane == 0) {
        g_gates[row * 3 + 0] = 1.f / (1.f + __expf(-(a0 + bg[0])));
        g_gates[row * 3 + 1] = 1.f / (1.f + __expf(-(a1 + bg[1])));
        g_gates[row * 3 + 2] = 1.f / (1.f + __expf(-(a2 + bg[2])));
    }
}

// ---------------- fused combine + bf16-split --------------------------------------------
__global__ __launch_bounds__(256) void combine_split_kernel()
{
    int idx = (blockIdx.x * 256 + threadIdx.x) * 4;
    int bs = idx >> 10;
    float g0 = g_gates[bs * 3 + 0];
    float g1 = g_gates[bs * 3 + 1];
    float g2 = g_gates[bs * 3 + 2];
    float4 oc = *(const float4*)(g_oc + idx);
    float4 os = *(const float4*)(g_os + idx);
    float4 ow = *(const float4*)(g_ow + idx);
    float v0 = g0 * oc.x + g1 * os.x + g2 * ow.x;
    float v1 = g0 * oc.y + g1 * os.y + g2 * ow.y;
    float v2 = g0 * oc.z + g1 * os.z + g2 * ow.z;
    float v3 = g0 * oc.w + g1 * os.w + g2 * ow.w;
    __nv_bfloat16 h0 = __float2bfloat16(v0), h1 = __float2bfloat16(v1);
    __nv_bfloat16 h2 = __float2bfloat16(v2), h3 = __float2bfloat16(v3);
    *(__nv_bfloat162*)(g_ah + idx)     = __halves2bfloat162(h0, h1);
    *(__nv_bfloat162*)(g_ah + idx + 2) = __halves2bfloat162(h2, h3);
    *(__nv_bfloat162*)(g_al + idx) = __halves2bfloat162(
        __float2bfloat16(v0 - __bfloat162float(h0)),
        __float2bfloat16(v1 - __bfloat162float(h1)));
    *(__nv_bfloat162*)(g_al + idx + 2) = __halves2bfloat162(
        __float2bfloat16(v2 - __bfloat162float(h2)),
        __float2bfloat16(v3 - __bfloat162float(h3)));
}

// ---------------- launcher ---------------------------------------------------------------
extern "C" void kernel_launch(void* const* d_in, const int* in_sizes, int n_in,
                              void* d_out, int out_size)
{
    (void)in_sizes; (void)n_in; (void)out_size;
    const float* x   = (const float*)d_in[0];
    const float* Wq  = (const float*)d_in[1];
    const float* Wk  = (const float*)d_in[2];
    const float* Wv  = (const float*)d_in[3];
    const float* Wo  = (const float*)d_in[4];
    const float* bo  = (const float*)d_in[5];
    const float* Wg  = (const float*)d_in[6];
    const float* bg  = (const float*)d_in[7];
    const float* wkc = (const float*)d_in[8];
    const float* wvc = (const float*)d_in[9];
    const float* wpe = (const float*)d_in[10];
    float* out = (float*)d_out;

    void *pq, *pk, *pv, *pah, *pal, *pwh, *pwl, *pwoh, *pwol;
    void *pxkc, *pxvc, *pck, *pcv, *ptt, *pimp, *ppec, *ppvc, *pttp, *pimpp;
    cudaGetSymbolAddress(&pq,   g_q);
    cudaGetSymbolAddress(&pk,   g_k);
    cudaGetSymbolAddress(&pv,   g_v);
    cudaGetSymbolAddress(&pah,  g_ah);
    cudaGetSymbolAddress(&pal,  g_al);
    cudaGetSymbolAddress(&pwh,  g_wh);
    cudaGetSymbolAddress(&pwl,  g_wl);
    cudaGetSymbolAddress(&pwoh, g_woh);
    cudaGetSymbolAddress(&pwol, g_wol);
    cudaGetSymbolAddress(&pxkc, g_xkc);
    cudaGetSymbolAddress(&pxvc, g_xvc);
    cudaGetSymbolAddress(&pck,  g_ck);
    cudaGetSymbolAddress(&pcv,  g_cv);
    cudaGetSymbolAddress(&ptt,  g_tt);
    cudaGetSymbolAddress(&pimp, g_imp);
    cudaGetSymbolAddress(&ppec, g_pec);
    cudaGetSymbolAddress(&ppvc, g_pvc);
    cudaGetSymbolAddress(&pttp, g_ttp);
    cudaGetSymbolAddress(&pimpp, g_impp);

    const __nv_bfloat16* ah  = (const __nv_bfloat16*)pah;
    const __nv_bfloat16* alo = (const __nv_bfloat16*)pal;
    const int NEL = NB * NS * ND;

    static bool inited = false;
    static cudaStream_t sB, sC;
    static cudaEvent_t e0, e1, eB, eC, eW;
    if (!inited) {
        cudaStreamCreateWithFlags(&sB, cudaStreamNonBlocking);
        cudaStreamCreateWithFlags(&sC, cudaStreamNonBlocking);
        cudaEventCreateWithFlags(&e0, cudaEventDisableTiming);
        cudaEventCreateWithFlags(&e1, cudaEventDisableTiming);
        cudaEventCreateWithFlags(&eB, cudaEventDisableTiming);
        cudaEventCreateWithFlags(&eC, cudaEventDisableTiming);
        cudaEventCreateWithFlags(&eW, cudaEventDisableTiming);
        cudaFuncSetAttribute(mma_gemm3_kernel,
                             cudaFuncAttributeMaxDynamicSharedMemorySize, SMEM_GEMM);
        cudaFuncSetAttribute(win_attn_kernel,
                             cudaFuncAttributeMaxDynamicSharedMemorySize, SMEM_ATT);
        cudaFuncSetAttribute(comp_attn_tile_kernel,
                             cudaFuncAttributeMaxDynamicSharedMemorySize, SMEM_ATT);
        inited = true;
    }

    cudaEventRecord(e0, 0);
    cudaStreamWaitEvent(sB, e0, 0);
    cudaStreamWaitEvent(sC, e0, 0);

    // ---- stream C: QKV weight conversion (parallel with split), then gates + Wo ----
    convert_w3_kernel<<<dim3(32, 32, 3), 256, 0, sC>>>(
        Wq, Wk, Wv, (__nv_bfloat16*)pwh, (__nv_bfloat16*)pwl);
    cudaEventRecord(eW, sC);
    gate_kernel<<<(NB * NS) / 8, 256, 0, sC>>>(x, Wg, bg);
    convert_w1_kernel<<<dim3(32, 32), 256, 0, sC>>>(
        Wo, (__nv_bfloat16*)pwoh, (__nv_bfloat16*)pwol);
    cudaEventRecord(eC, sC);

    // ---- main stream: split x, then QKV GEMM ----
    split_kernel<<<NEL / 1024, 256>>>(x, (__nv_bfloat16*)pah, (__nv_bfloat16*)pal);
    cudaStreamWaitEvent(0, eW, 0);
    mma_gemm3_kernel<<<dim3(24, 16), 256, SMEM_GEMM>>>(
        ah, alo, (const __nv_bfloat16*)pwh, (const __nv_bfloat16*)pwl,
        (float*)pq, (float*)pk, (float*)pv, wpe, 1);
    cudaEventRecord(e1, 0);

    // ---- stream B: exact fp32 top-k chain ----
    xc_kernel<<<(NB * NNC * ND) / 256, 256, 0, sB>>>(x, wkc, wvc);
    pe_comb_kernel<<<ND / 256, 256, 0, sB>>>(wpe, wkc, wvc);
    csgemm_kernel<<<dim3(16, 1, 8), 256, 0, sB>>>(
        (const float*)pxkc, (const float*)pxvc, Wk, Wv);
    reduce_ckcv_kernel<<<(2 * 131072) / 256, 256, 0, sB>>>(
        (const float*)ppec, (const float*)ppvc);
    nt_gemm_kernel<<<dim3(16, 1, 8), 256, 0, sB>>>(
        (const float*)pck, Wq, (float*)pttp, 1024, 64L * 1024, 0L, 64L * 1024);
    reduce4_kernel<<<(NB * 65536) / 256, 256, 0, sB>>>(
        (const float*)pttp, (float*)ptt, 65536);
    nt_gemm_kernel<<<dim3(1, 16, 8), 256, 0, sB>>>(
        x, (const float*)ptt, (float*)pimpp, 64, 1024L * 1024, 64L * 1024, 1024L * 64);
    reduce4_kernel<<<(NB * 65536) / 256, 256, 0, sB>>>(
        (const float*)pimpp, (float*)pimp, 65536);
    top2_kernel<<<(NB * NS) / 8, 256, 0, sB>>>();
    cudaStreamWaitEvent(sB, e1, 0);
    comp_attn_tile_kernel<<<dim3(16, 16, 2), 256, SMEM_ATT, sB>>>();
    sel_attn_kernel<<<NB * NS, 512, 0, sB>>>();
    cudaEventRecord(eB, sB);

    // ---- main: window attention, join, fused combine+split, OUT GEMM ----
    win_attn_kernel<<<dim3(NS / 64, NH, NB), 256, SMEM_ATT>>>();
    cudaStreamWaitEvent(0, eB, 0);
    cudaStreamWaitEvent(0, eC, 0);
    combine_split_kernel<<<NEL / 1024, 256>>>();
    mma_gemm3_kernel<<<dim3(8, 16), 256, SMEM_GEMM>>>(
        ah, alo, (const __nv_bfloat16*)pwoh, (const __nv_bfloat16*)pwol,
        out, out, out, bo, 0);
}